// round 14
// baseline (speedup 1.0000x reference)
#include <cuda_runtime.h>
#include <cuda_fp16.h>
#include <cstdint>

#define T_STEPS 512
#define BATCH   2048
#define IN_DIM  12
#define E_DIM   15
#define H_DIM   20
#define XS      (BATCH * IN_DIM)
#define OS      (BATCH * 3)
#define TPAD    (T_STEPS + 4)         // prefetch pad
#define GSTEP   8                     // timesteps per xgate group
#define NGROUP  (T_STEPS / GSTEP)     // 64

typedef unsigned long long u64;
typedef uint32_t u32;

// Scratch: x-gate pre-activations as half4 (i,f,g,o) = one u64 per (b,t,cell).
// Layout [b][t][cell].
__device__ __align__(16) u64    g_xg[(size_t)BATCH * TPAD * H_DIM];
__device__ __align__(16) u64    g_wcx[4][H_DIM][6];
__device__ __align__(16) float4 g_bc4[H_DIM];

__device__ __forceinline__ u64 pack2(float x, float y) {
    u64 u; asm("mov.b64 %0, {%1, %2};" : "=l"(u) : "f"(x), "f"(y)); return u;
}
__device__ __forceinline__ void unpack2(float& x, float& y, u64 u) {
    asm("mov.b64 {%0, %1}, %2;" : "=f"(x), "=f"(y) : "l"(u));
}
__device__ __forceinline__ u64 pack2u(u32 lo, u32 hi) {
    u64 u; asm("mov.b64 %0, {%1, %2};" : "=l"(u) : "r"(lo), "r"(hi)); return u;
}
__device__ __forceinline__ void unpack2u(u32& lo, u32& hi, u64 u) {
    asm("mov.b64 {%0, %1}, %2;" : "=r"(lo), "=r"(hi) : "l"(u));
}
__device__ __forceinline__ void fma2(u64& d, u64 a, u64 b) {
    asm("fma.rn.f32x2 %0, %1, %2, %0;" : "+l"(d) : "l"(a), "l"(b));
}
__device__ __forceinline__ float hsum2(u64 u) {
    float x, y; unpack2(x, y, u); return x + y;
}
__device__ __forceinline__ float tanh_a(float x) {
    float y; asm("tanh.approx.f32 %0, %1;" : "=f"(y) : "f"(x)); return y;
}
__device__ __forceinline__ float sig_a(float x) {
    return fmaf(0.5f, tanh_a(0.5f * x), 0.5f);
}
__device__ __forceinline__ u32 saddr(const void* p) {
    return (u32)__cvta_generic_to_shared(p);
}
__device__ __forceinline__ void lds2d(u64& a, u64& b, u32 addr) {
    asm volatile("ld.shared.v2.b64 {%0, %1}, [%2];" : "=l"(a), "=l"(b) : "r"(addr));
}
__device__ __forceinline__ void sts64d(u32 addr, u64 v) {
    asm volatile("st.shared.b64 [%0], %1;" :: "r"(addr), "l"(v));
}
__device__ __forceinline__ void ldg2(u64& a, u64& b, const void* p) {
    asm volatile("ld.global.v2.b64 {%0, %1}, [%2];" : "=l"(a), "=l"(b) : "l"(p));
}
__device__ __forceinline__ void ldg1(u64& a, const void* p) {
    asm volatile("ld.global.b64 %0, [%1];" : "=l"(a) : "l"(p));
}
__device__ __forceinline__ float2 h2f(u32 v) {
    __half2 h = *reinterpret_cast<__half2*>(&v);
    return __half22float2(h);
}

// ============ Kernel 0: fuse Wc = Wih@Wemb, bc once ============
__global__ void prep_kernel(const float* __restrict__ Wemb, const float* __restrict__ bemb,
                            const float* __restrict__ Wih,  const float* __restrict__ bih,
                            const float* __restrict__ bhh)
{
    const int tid = threadIdx.x;
    for (int i = tid; i < 480; i += blockDim.x) {
        const int g = i / 120, rem = i - g * 120;
        const int k = rem / 6, jj = rem - k * 6;
        const int r = g * H_DIM + k;
        float c0 = 0.f, c1 = 0.f;
#pragma unroll
        for (int e = 0; e < E_DIM; ++e) {
            const float wie = Wih[r * E_DIM + e];
            c0 += wie * Wemb[e * IN_DIM + 2 * jj];
            c1 += wie * Wemb[e * IN_DIM + 2 * jj + 1];
        }
        g_wcx[g][k][jj] = pack2(c0, c1);
    }
    if (tid < H_DIM) {
        float4 b4;
        float* bp = &b4.x;
#pragma unroll
        for (int g = 0; g < 4; ++g) {
            const int r = g * H_DIM + tid;
            float b = bih[r] + bhh[r];
#pragma unroll
            for (int e = 0; e < E_DIM; ++e) b += Wih[r * E_DIM + e] * bemb[e];
            bp[g] = b;
        }
        g_bc4[tid] = b4;
    }
}

// ============ Kernel 1: x-gate precompute (full-lane version) ============
// Block = 160 threads = 20 cells x 8 timesteps. Thread (tl, c) owns cell c at
// timestep t0+tl; weights register-stationary; x staged via smem (coalesced);
// scratch stores perfectly coalesced (in-block store index == tid).
__global__ void __launch_bounds__(160, 4)
xgate_kernel(const float* __restrict__ X)
{
    __shared__ __align__(16) float xs[2][GSTEP][IN_DIM];   // 2 x 8 x 12 floats

    const int tid = threadIdx.x;
    const int b   = blockIdx.x;
    const int tl  = tid / H_DIM;      // 0..7 timestep-in-group
    const int c   = tid - tl * H_DIM; // 0..19 cell

    // register-stationary fused weights + bias for this cell
    u64 wg[4][6];
#pragma unroll
    for (int g = 0; g < 4; ++g) {
        ldg2(wg[g][0], wg[g][1], &g_wcx[g][c][0]);
        ldg2(wg[g][2], wg[g][3], &g_wcx[g][c][2]);
        ldg2(wg[g][4], wg[g][5], &g_wcx[g][c][4]);
    }
    const float4 b4 = g_bc4[c];

    // staging assignment: threads 0..95 load (stl, j)
    const int stl = tid / IN_DIM;     // 0..7 for tid<96
    const int sj  = tid - stl * IN_DIM;
    const bool stager = tid < GSTEP * IN_DIM;
    const long long xoff = (long long)b * IN_DIM + sj;

    if (stager) xs[0][stl][sj] = X[(long long)stl * XS + xoff];
    __syncthreads();

    const u32 xsa0 = saddr(&xs[0][tl][0]);
    const u32 xsa1 = saddr(&xs[1][tl][0]);
    u64* op = g_xg + ((size_t)b * TPAD + tl) * H_DIM + c;

#pragma unroll 1
    for (int g0 = 0; g0 < NGROUP; ++g0) {
        // prefetch next group's x (consumed after the barrier below)
        float xv = 0.f;
        const bool st = stager && (g0 + 1 < NGROUP);
        if (st) xv = X[(long long)((g0 + 1) * GSTEP + stl) * XS + xoff];

        // compute this thread's (b, t0+tl, c) gate quad
        const u32 xa = (g0 & 1) ? xsa1 : xsa0;
        u64 x0, x1, x2, x3, x4, x5;
        lds2d(x0, x1, xa);
        lds2d(x2, x3, xa + 16);
        lds2d(x4, x5, xa + 32);
        u64 a0 = pack2(b4.x, 0.f), a1 = pack2(b4.y, 0.f);
        u64 a2 = pack2(b4.z, 0.f), a3 = pack2(b4.w, 0.f);
        fma2(a0, wg[0][0], x0); fma2(a1, wg[1][0], x0); fma2(a2, wg[2][0], x0); fma2(a3, wg[3][0], x0);
        fma2(a0, wg[0][1], x1); fma2(a1, wg[1][1], x1); fma2(a2, wg[2][1], x1); fma2(a3, wg[3][1], x1);
        fma2(a0, wg[0][2], x2); fma2(a1, wg[1][2], x2); fma2(a2, wg[2][2], x2); fma2(a3, wg[3][2], x2);
        fma2(a0, wg[0][3], x3); fma2(a1, wg[1][3], x3); fma2(a2, wg[2][3], x3); fma2(a3, wg[3][3], x3);
        fma2(a0, wg[0][4], x4); fma2(a1, wg[1][4], x4); fma2(a2, wg[2][4], x4); fma2(a3, wg[3][4], x4);
        fma2(a0, wg[0][5], x5); fma2(a1, wg[1][5], x5); fma2(a2, wg[2][5], x5); fma2(a3, wg[3][5], x5);
        __half2 hl = __floats2half2_rn(hsum2(a0), hsum2(a1));
        __half2 hh = __floats2half2_rn(hsum2(a2), hsum2(a3));
        *op = pack2u(*reinterpret_cast<u32*>(&hl), *reinterpret_cast<u32*>(&hh));
        op += GSTEP * H_DIM;

        if (st) xs[(g0 + 1) & 1][stl][sj] = xv;
        __syncthreads();
    }
}

// ============ Kernel 2: recurrence (R12 form: 1 row per warp) ============
__global__ void __launch_bounds__(32, 14)
lstm_kernel(const float* __restrict__ Whh,
            const float* __restrict__ Wout, const float* __restrict__ bout,
            float* __restrict__ out)
{
    __shared__ __align__(16) u64 hdup[2][H_DIM];   // (h,h) pairs, ping-pong

    const int lane = threadIdx.x;
    const int grow = blockIdx.x;
    const bool hL = lane < H_DIM;
    const bool oL = (lane >= H_DIM) && (lane < H_DIM + 3);
    const int k   = hL ? lane : 0;

    u64 w01[H_DIM], w23[H_DIM];
    u64 bO = 0ull;
    if (hL) {
#pragma unroll
        for (int j = 0; j < H_DIM; ++j) {
            w01[j] = pack2(Whh[lane * H_DIM + j],               Whh[(H_DIM + lane) * H_DIM + j]);
            w23[j] = pack2(Whh[(2 * H_DIM + lane) * H_DIM + j], Whh[(3 * H_DIM + lane) * H_DIM + j]);
        }
    } else {
#pragma unroll
        for (int j = 0; j < H_DIM; ++j) { w01[j] = 0ull; w23[j] = 0ull; }
        if (oL) {
            const int m = lane - H_DIM;
#pragma unroll
            for (int j = 0; j < H_DIM; ++j) w01[j] = pack2(Wout[m * H_DIM + j], 0.f);
            bO = pack2(bout[m], 0.f);
        }
    }
    if (hL) hdup[0][lane] = 0ull;
    __syncwarp();

    const u32 h0a = saddr(&hdup[0][0]);
    const u32 h1a = saddr(&hdup[1][0]);
    const u32 hw0 = h0a + lane * 8;
    const u32 hw1 = h1a + lane * 8;

    const u64* gp = g_xg + (size_t)grow * TPAD * H_DIM + k;
    u64 pa, pb, pc, pd;
    ldg1(pa, gp);
    ldg1(pb, gp + H_DIM);
    ldg1(pc, gp + 2 * H_DIM);
    ldg1(pd, gp + 3 * H_DIM);
    gp += 4 * H_DIM;

    float c = 0.f;
    float* outp = out + (long long)grow * 3 + (lane - H_DIM) - OS;

#define STEP(PX, HRD, HWR, DOOUT)                                              \
    do {                                                                       \
        u32 xl, xh; unpack2u(xl, xh, (PX));                                    \
        const float2 flo = h2f(xl);                                            \
        const float2 fhi = h2f(xh);                                            \
        u64 a01 = hL ? pack2(flo.x, flo.y) : bO;                               \
        u64 a23 = pack2(fhi.x, fhi.y);                                         \
        u64 a01b = 0ull, a23b = 0ull;                                          \
        u64 e0, e1, e2, e3;                                                    \
        lds2d(e0, e1, (HRD));        lds2d(e2, e3, (HRD) + 16);                \
        fma2(a01, w01[0], e0); fma2(a23, w23[0], e0);                          \
        fma2(a01, w01[1], e1); fma2(a23, w23[1], e1);                          \
        fma2(a01, w01[2], e2); fma2(a23, w23[2], e2);                          \
        fma2(a01, w01[3], e3); fma2(a23, w23[3], e3);                          \
        lds2d(e0, e1, (HRD) + 32);   lds2d(e2, e3, (HRD) + 48);                \
        fma2(a01, w01[4], e0); fma2(a23, w23[4], e0);                          \
        fma2(a01, w01[5], e1); fma2(a23, w23[5], e1);                          \
        fma2(a01, w01[6], e2); fma2(a23, w23[6], e2);                          \
        fma2(a01, w01[7], e3); fma2(a23, w23[7], e3);                          \
        lds2d(e0, e1, (HRD) + 64);   lds2d(e2, e3, (HRD) + 80);                \
        fma2(a01, w01[8],  e0); fma2(a23, w23[8],  e0);                        \
        fma2(a01, w01[9],  e1); fma2(a23, w23[9],  e1);                        \
        fma2(a01b, w01[10], e2); fma2(a23b, w23[10], e2);                      \
        fma2(a01b, w01[11], e3); fma2(a23b, w23[11], e3);                      \
        lds2d(e0, e1, (HRD) + 96);   lds2d(e2, e3, (HRD) + 112);               \
        fma2(a01b, w01[12], e0); fma2(a23b, w23[12], e0);                      \
        fma2(a01b, w01[13], e1); fma2(a23b, w23[13], e1);                      \
        fma2(a01b, w01[14], e2); fma2(a23b, w23[14], e2);                      \
        fma2(a01b, w01[15], e3); fma2(a23b, w23[15], e3);                      \
        lds2d(e0, e1, (HRD) + 128);  lds2d(e2, e3, (HRD) + 144);               \
        fma2(a01b, w01[16], e0); fma2(a23b, w23[16], e0);                      \
        fma2(a01b, w01[17], e1); fma2(a23b, w23[17], e1);                      \
        fma2(a01b, w01[18], e2); fma2(a23b, w23[18], e2);                      \
        fma2(a01b, w01[19], e3); fma2(a23b, w23[19], e3);                      \
        asm("add.rn.f32x2 %0, %0, %1;" : "+l"(a01) : "l"(a01b));               \
        asm("add.rn.f32x2 %0, %0, %1;" : "+l"(a23) : "l"(a23b));               \
        float p0, p1, p2, p3;                                                  \
        unpack2(p0, p1, a01); unpack2(p2, p3, a23);                            \
        const float iv = sig_a(p0), fv = sig_a(p1);                            \
        const float gv = tanh_a(p2), ov = sig_a(p3);                           \
        c = fmaf(fv, c, iv * gv);                                              \
        const float h = ov * tanh_a(c);                                        \
        if (hL) sts64d((HWR), pack2(h, h));                                    \
        if (oL && (DOOUT)) *outp = p0;                                         \
        outp += OS;                                                            \
        ldg1((PX), gp); gp += H_DIM;                                           \
        __syncwarp();                                                          \
    } while (0)

    STEP(pa, h0a, hw1, false);
    STEP(pb, h1a, hw0, true);
    STEP(pc, h0a, hw1, true);
    STEP(pd, h1a, hw0, true);
#pragma unroll 1
    for (int t4 = 4; t4 < T_STEPS; t4 += 4) {
        STEP(pa, h0a, hw1, true);
        STEP(pb, h1a, hw0, true);
        STEP(pc, h0a, hw1, true);
        STEP(pd, h1a, hw0, true);
    }
#undef STEP

    // final out[T-1] from h_511 (in buf 0)
    {
        u64 a01 = bO;
        u64 e0, e1, e2, e3;
#pragma unroll
        for (int q = 0; q < 5; ++q) {
            lds2d(e0, e1, h0a + q * 32);
            lds2d(e2, e3, h0a + q * 32 + 16);
            fma2(a01, w01[4 * q],     e0); fma2(a01, w01[4 * q + 1], e1);
            fma2(a01, w01[4 * q + 2], e2); fma2(a01, w01[4 * q + 3], e3);
        }
        if (oL) {
            float v, d; unpack2(v, d, a01);
            *outp = v;
        }
    }
}

extern "C" void kernel_launch(void* const* d_in, const int* in_sizes, int n_in,
                              void* d_out, int out_size) {
    const float* X    = (const float*)d_in[0];
    const float* Wemb = (const float*)d_in[1];
    const float* bemb = (const float*)d_in[2];
    const float* Wih  = (const float*)d_in[3];
    const float* bih  = (const float*)d_in[4];
    const float* Whh  = (const float*)d_in[5];
    const float* bhh  = (const float*)d_in[6];
    const float* Wout = (const float*)d_in[7];
    const float* bout = (const float*)d_in[8];
    float* out = (float*)d_out;

    prep_kernel<<<1, 256>>>(Wemb, bemb, Wih, bih, bhh);
    xgate_kernel<<<BATCH, 160>>>(X);
    lstm_kernel<<<BATCH, 32>>>(Whh, Wout, bout, out);
}

// round 15
// speedup vs baseline: 1.2082x; 1.2082x over previous
#include <cuda_runtime.h>
#include <cuda_fp16.h>
#include <cstdint>

#define T_STEPS 512
#define BATCH   2048
#define IN_DIM  12
#define E_DIM   15
#define H_DIM   20
#define XS      (BATCH * IN_DIM)
#define OS      (BATCH * 3)
#define TCHUNKS 8
#define TPERC   (T_STEPS / TCHUNKS)   // 64
#define TPAD    (T_STEPS + 4)         // prefetch pad

typedef unsigned long long u64;
typedef uint32_t u32;

// Scratch: x-gate pre-activations as half4 (i,f,g,o) = one u64 per (b,t,cell).
__device__ __align__(16) u64    g_xg[(size_t)BATCH * TPAD * H_DIM];
__device__ __align__(16) u64    g_wcx[4][H_DIM][6];
__device__ __align__(16) float4 g_bc4[H_DIM];

__device__ __forceinline__ u64 pack2(float x, float y) {
    u64 u; asm("mov.b64 %0, {%1, %2};" : "=l"(u) : "f"(x), "f"(y)); return u;
}
__device__ __forceinline__ void unpack2(float& x, float& y, u64 u) {
    asm("mov.b64 {%0, %1}, %2;" : "=f"(x), "=f"(y) : "l"(u));
}
__device__ __forceinline__ u64 pack2u(u32 lo, u32 hi) {
    u64 u; asm("mov.b64 %0, {%1, %2};" : "=l"(u) : "r"(lo), "r"(hi)); return u;
}
__device__ __forceinline__ void unpack2u(u32& lo, u32& hi, u64 u) {
    asm("mov.b64 {%0, %1}, %2;" : "=r"(lo), "=r"(hi) : "l"(u));
}
__device__ __forceinline__ void fma2(u64& d, u64 a, u64 b) {
    asm("fma.rn.f32x2 %0, %1, %2, %0;" : "+l"(d) : "l"(a), "l"(b));
}
__device__ __forceinline__ float hsum2(u64 u) {
    float x, y; unpack2(x, y, u); return x + y;
}
__device__ __forceinline__ float tanh_a(float x) {
    float y; asm("tanh.approx.f32 %0, %1;" : "=f"(y) : "f"(x)); return y;
}
__device__ __forceinline__ float sig_a(float x) {
    return fmaf(0.5f, tanh_a(0.5f * x), 0.5f);
}
__device__ __forceinline__ u32 saddr(const void* p) {
    return (u32)__cvta_generic_to_shared(p);
}
__device__ __forceinline__ void lds2d(u64& a, u64& b, u32 addr) {
    asm volatile("ld.shared.v2.b64 {%0, %1}, [%2];" : "=l"(a), "=l"(b) : "r"(addr));
}
__device__ __forceinline__ void sts64d(u32 addr, u64 v) {
    asm volatile("st.shared.b64 [%0], %1;" :: "r"(addr), "l"(v));
}
__device__ __forceinline__ void ldg2(u64& a, u64& b, const void* p) {
    asm volatile("ld.global.v2.b64 {%0, %1}, [%2];" : "=l"(a), "=l"(b) : "l"(p));
}
__device__ __forceinline__ void ldg1(u64& a, const void* p) {
    asm volatile("ld.global.b64 %0, [%1];" : "=l"(a) : "l"(p));
}
__device__ __forceinline__ float2 h2f(u32 v) {
    __half2 h = *reinterpret_cast<__half2*>(&v);
    return __half22float2(h);
}

// ============ Kernel 0: fuse Wc = Wih@Wemb, bc once ============
__global__ void prep_kernel(const float* __restrict__ Wemb, const float* __restrict__ bemb,
                            const float* __restrict__ Wih,  const float* __restrict__ bih,
                            const float* __restrict__ bhh)
{
    const int tid = threadIdx.x;
    for (int i = tid; i < 480; i += blockDim.x) {
        const int g = i / 120, rem = i - g * 120;
        const int k = rem / 6, jj = rem - k * 6;
        const int r = g * H_DIM + k;
        float c0 = 0.f, c1 = 0.f;
#pragma unroll
        for (int e = 0; e < E_DIM; ++e) {
            const float wie = Wih[r * E_DIM + e];
            c0 += wie * Wemb[e * IN_DIM + 2 * jj];
            c1 += wie * Wemb[e * IN_DIM + 2 * jj + 1];
        }
        g_wcx[g][k][jj] = pack2(c0, c1);
    }
    if (tid < H_DIM) {
        float4 b4;
        float* bp = &b4.x;
#pragma unroll
        for (int g = 0; g < 4; ++g) {
            const int r = g * H_DIM + tid;
            float b = bih[r] + bhh[r];
#pragma unroll
            for (int e = 0; e < E_DIM; ++e) b += Wih[r * E_DIM + e] * bemb[e];
            bp[g] = b;
        }
        g_bc4[tid] = b4;
    }
}

// ============ Kernel 1: x-gate precompute, 4-deep LDG pipeline ============
// warp = (batch row b, 64-step t-chunk). Lane k<20 owns cell k (4 gates).
__global__ void __launch_bounds__(32, 16)
xgate_kernel(const float* __restrict__ X)
{
    const int lane = threadIdx.x;
    const int b    = blockIdx.x;
    const int tc   = blockIdx.y;
    const int k    = (lane < H_DIM) ? lane : 0;

    u64 wg[4][6];
#pragma unroll
    for (int g = 0; g < 4; ++g) {
        ldg2(wg[g][0], wg[g][1], &g_wcx[g][k][0]);
        ldg2(wg[g][2], wg[g][3], &g_wcx[g][k][2]);
        ldg2(wg[g][4], wg[g][5], &g_wcx[g][k][4]);
    }
    const float4 b4 = g_bc4[k];

    const float* xp = X + (long long)(tc * TPERC) * XS + (long long)b * IN_DIM;
    u64* op = g_xg + ((size_t)b * TPAD + tc * TPERC) * H_DIM + k;

    // 4-deep register ring of x (6 u64 per timestep)
    u64 xr[4][6];
#pragma unroll
    for (int p = 0; p < 4; ++p) {
        ldg2(xr[p][0], xr[p][1], xp);
        ldg2(xr[p][2], xr[p][3], xp + 4);
        ldg2(xr[p][4], xr[p][5], xp + 8);
        xp += XS;
    }

#pragma unroll 4
    for (int it = 0; it < TPERC; ++it) {
        const int sl = it & 3;
        u64 a0 = pack2(b4.x, 0.f), a1 = pack2(b4.y, 0.f);
        u64 a2 = pack2(b4.z, 0.f), a3 = pack2(b4.w, 0.f);
#pragma unroll
        for (int j = 0; j < 6; ++j) {
            const u64 xv = xr[sl][j];
            fma2(a0, wg[0][j], xv); fma2(a1, wg[1][j], xv);
            fma2(a2, wg[2][j], xv); fma2(a3, wg[3][j], xv);
        }
        // prefetch it+4 into the slot just freed (issues before the dependent tail)
        if (it + 4 < TPERC) {
            ldg2(xr[sl][0], xr[sl][1], xp);
            ldg2(xr[sl][2], xr[sl][3], xp + 4);
            ldg2(xr[sl][4], xr[sl][5], xp + 8);
            xp += XS;
        }
        __half2 hl = __floats2half2_rn(hsum2(a0), hsum2(a1));
        __half2 hh = __floats2half2_rn(hsum2(a2), hsum2(a3));
        const u64 v = pack2u(*reinterpret_cast<u32*>(&hl),
                             *reinterpret_cast<u32*>(&hh));
        if (lane < H_DIM) *op = v;
        op += H_DIM;
    }
}

// ============ Kernel 2: recurrence (R12 form, unchanged) ============
__global__ void __launch_bounds__(32, 14)
lstm_kernel(const float* __restrict__ Whh,
            const float* __restrict__ Wout, const float* __restrict__ bout,
            float* __restrict__ out)
{
    __shared__ __align__(16) u64 hdup[2][H_DIM];   // (h,h) pairs, ping-pong

    const int lane = threadIdx.x;
    const int grow = blockIdx.x;
    const bool hL = lane < H_DIM;
    const bool oL = (lane >= H_DIM) && (lane < H_DIM + 3);
    const int k   = hL ? lane : 0;

    u64 w01[H_DIM], w23[H_DIM];
    u64 bO = 0ull;
    if (hL) {
#pragma unroll
        for (int j = 0; j < H_DIM; ++j) {
            w01[j] = pack2(Whh[lane * H_DIM + j],               Whh[(H_DIM + lane) * H_DIM + j]);
            w23[j] = pack2(Whh[(2 * H_DIM + lane) * H_DIM + j], Whh[(3 * H_DIM + lane) * H_DIM + j]);
        }
    } else {
#pragma unroll
        for (int j = 0; j < H_DIM; ++j) { w01[j] = 0ull; w23[j] = 0ull; }
        if (oL) {
            const int m = lane - H_DIM;
#pragma unroll
            for (int j = 0; j < H_DIM; ++j) w01[j] = pack2(Wout[m * H_DIM + j], 0.f);
            bO = pack2(bout[m], 0.f);
        }
    }
    if (hL) hdup[0][lane] = 0ull;
    __syncwarp();

    const u32 h0a = saddr(&hdup[0][0]);
    const u32 h1a = saddr(&hdup[1][0]);
    const u32 hw0 = h0a + lane * 8;
    const u32 hw1 = h1a + lane * 8;

    const u64* gp = g_xg + (size_t)grow * TPAD * H_DIM + k;
    u64 pa, pb, pc, pd;
    ldg1(pa, gp);
    ldg1(pb, gp + H_DIM);
    ldg1(pc, gp + 2 * H_DIM);
    ldg1(pd, gp + 3 * H_DIM);
    gp += 4 * H_DIM;

    float c = 0.f;
    float* outp = out + (long long)grow * 3 + (lane - H_DIM) - OS;

#define STEP(PX, HRD, HWR, DOOUT)                                              \
    do {                                                                       \
        u32 xl, xh; unpack2u(xl, xh, (PX));                                    \
        const float2 flo = h2f(xl);                                            \
        const float2 fhi = h2f(xh);                                            \
        u64 a01 = hL ? pack2(flo.x, flo.y) : bO;                               \
        u64 a23 = pack2(fhi.x, fhi.y);                                         \
        u64 a01b = 0ull, a23b = 0ull;                                          \
        u64 e0, e1, e2, e3;                                                    \
        lds2d(e0, e1, (HRD));        lds2d(e2, e3, (HRD) + 16);                \
        fma2(a01, w01[0], e0); fma2(a23, w23[0], e0);                          \
        fma2(a01, w01[1], e1); fma2(a23, w23[1], e1);                          \
        fma2(a01, w01[2], e2); fma2(a23, w23[2], e2);                          \
        fma2(a01, w01[3], e3); fma2(a23, w23[3], e3);                          \
        lds2d(e0, e1, (HRD) + 32);   lds2d(e2, e3, (HRD) + 48);                \
        fma2(a01, w01[4], e0); fma2(a23, w23[4], e0);                          \
        fma2(a01, w01[5], e1); fma2(a23, w23[5], e1);                          \
        fma2(a01, w01[6], e2); fma2(a23, w23[6], e2);                          \
        fma2(a01, w01[7], e3); fma2(a23, w23[7], e3);                          \
        lds2d(e0, e1, (HRD) + 64);   lds2d(e2, e3, (HRD) + 80);                \
        fma2(a01, w01[8],  e0); fma2(a23, w23[8],  e0);                        \
        fma2(a01, w01[9],  e1); fma2(a23, w23[9],  e1);                        \
        fma2(a01b, w01[10], e2); fma2(a23b, w23[10], e2);                      \
        fma2(a01b, w01[11], e3); fma2(a23b, w23[11], e3);                      \
        lds2d(e0, e1, (HRD) + 96);   lds2d(e2, e3, (HRD) + 112);               \
        fma2(a01b, w01[12], e0); fma2(a23b, w23[12], e0);                      \
        fma2(a01b, w01[13], e1); fma2(a23b, w23[13], e1);                      \
        fma2(a01b, w01[14], e2); fma2(a23b, w23[14], e2);                      \
        fma2(a01b, w01[15], e3); fma2(a23b, w23[15], e3);                      \
        lds2d(e0, e1, (HRD) + 128);  lds2d(e2, e3, (HRD) + 144);               \
        fma2(a01b, w01[16], e0); fma2(a23b, w23[16], e0);                      \
        fma2(a01b, w01[17], e1); fma2(a23b, w23[17], e1);                      \
        fma2(a01b, w01[18], e2); fma2(a23b, w23[18], e2);                      \
        fma2(a01b, w01[19], e3); fma2(a23b, w23[19], e3);                      \
        asm("add.rn.f32x2 %0, %0, %1;" : "+l"(a01) : "l"(a01b));               \
        asm("add.rn.f32x2 %0, %0, %1;" : "+l"(a23) : "l"(a23b));               \
        float p0, p1, p2, p3;                                                  \
        unpack2(p0, p1, a01); unpack2(p2, p3, a23);                            \
        const float iv = sig_a(p0), fv = sig_a(p1);                            \
        const float gv = tanh_a(p2), ov = sig_a(p3);                           \
        c = fmaf(fv, c, iv * gv);                                              \
        const float h = ov * tanh_a(c);                                        \
        if (hL) sts64d((HWR), pack2(h, h));                                    \
        if (oL && (DOOUT)) *outp = p0;                                         \
        outp += OS;                                                            \
        ldg1((PX), gp); gp += H_DIM;                                           \
        __syncwarp();                                                          \
    } while (0)

    STEP(pa, h0a, hw1, false);
    STEP(pb, h1a, hw0, true);
    STEP(pc, h0a, hw1, true);
    STEP(pd, h1a, hw0, true);
#pragma unroll 1
    for (int t4 = 4; t4 < T_STEPS; t4 += 4) {
        STEP(pa, h0a, hw1, true);
        STEP(pb, h1a, hw0, true);
        STEP(pc, h0a, hw1, true);
        STEP(pd, h1a, hw0, true);
    }
#undef STEP

    // final out[T-1] from h_511 (in buf 0)
    {
        u64 a01 = bO;
        u64 e0, e1, e2, e3;
#pragma unroll
        for (int q = 0; q < 5; ++q) {
            lds2d(e0, e1, h0a + q * 32);
            lds2d(e2, e3, h0a + q * 32 + 16);
            fma2(a01, w01[4 * q],     e0); fma2(a01, w01[4 * q + 1], e1);
            fma2(a01, w01[4 * q + 2], e2); fma2(a01, w01[4 * q + 3], e3);
        }
        if (oL) {
            float v, d; unpack2(v, d, a01);
            *outp = v;
        }
    }
}

extern "C" void kernel_launch(void* const* d_in, const int* in_sizes, int n_in,
                              void* d_out, int out_size) {
    const float* X    = (const float*)d_in[0];
    const float* Wemb = (const float*)d_in[1];
    const float* bemb = (const float*)d_in[2];
    const float* Wih  = (const float*)d_in[3];
    const float* bih  = (const float*)d_in[4];
    const float* Whh  = (const float*)d_in[5];
    const float* bhh  = (const float*)d_in[6];
    const float* Wout = (const float*)d_in[7];
    const float* bout = (const float*)d_in[8];
    float* out = (float*)d_out;

    prep_kernel<<<1, 256>>>(Wemb, bemb, Wih, bih, bhh);
    dim3 g1(BATCH, TCHUNKS);
    xgate_kernel<<<g1, 32>>>(X);
    lstm_kernel<<<BATCH, 32>>>(Whh, Wout, bout, out);
}